// round 1
// baseline (speedup 1.0000x reference)
#include <cuda_runtime.h>
#include <cstdint>
#include <cstddef>

#define N_NODES_C 50000
#define N_EDGES_C 625000
#define HID 128
#define TE 128
#define NTHREADS 256

// 25.6 MB scratch for pooled messages (allocation-free scratch via __device__ global)
__device__ float g_pooled[(size_t)N_NODES_C * HID];

__device__ __forceinline__ unsigned long long ffma2(unsigned long long a,
                                                    unsigned long long b,
                                                    unsigned long long c) {
    unsigned long long d;
    asm("fma.rn.f32x2 %0, %1, %2, %3;" : "=l"(d) : "l"(a), "l"(b), "l"(c));
    return d;
}

__device__ __forceinline__ void red_add_v4(float* p, float a, float b, float c, float d) {
    asm volatile("red.global.add.v4.f32 [%0], {%1, %2, %3, %4};"
                 :: "l"(p), "f"(a), "f"(b), "f"(c), "f"(d) : "memory");
}

// One kernel template for both GEMMs.
// EDGE_MODE=true : rows gathered via src; epilogue = gcn_norm * relu(.+bias), red-scatter by tgt into out(=pooled)
// EDGE_MODE=false: rows are direct;      epilogue = relu(.+bias) + resid, direct store into out
template<bool EDGE_MODE>
__global__ void __launch_bounds__(NTHREADS, 1)
fused_gemm(const float* __restrict__ X,
           const float* __restrict__ W,      // [HID, HID] row-major: out[c] = sum_k in[k]*W[k*HID+c]
           const float* __restrict__ bias,   // [HID]
           const int*   __restrict__ src,
           const int*   __restrict__ tgt,
           const float* __restrict__ nrm,
           const float* __restrict__ resid,
           float*       __restrict__ out,
           int n_rows)
{
    extern __shared__ float smem[];
    float* Wd = smem;                    // HID x (2*HID): Wd[k*256 + 2c] = Wd[k*256+2c+1] = W[k][c]
    float* Hs = smem + HID * 2 * HID;    // k-major tile: Hs[k*TE + e]

    const int tid = threadIdx.x;

    // ---- Load W into duplicated layout (once per block, persistent grid) ----
    for (int i = tid; i < HID * HID / 4; i += NTHREADS) {
        float4 w = __ldg((const float4*)W + i);
        int k = (i * 4) / HID;
        int c = (i * 4) % HID;
        float* d = &Wd[k * 2 * HID + 2 * c];
        d[0] = w.x; d[1] = w.x;
        d[2] = w.y; d[3] = w.y;
        d[4] = w.z; d[5] = w.z;
        d[6] = w.w; d[7] = w.w;
    }

    const int tx = tid & 15;   // column group 0..15
    const int ty = tid >> 4;   // row group    0..15
    const int c0 = tx * 4;     // cols [c0..c0+3] and [64+c0..64+c0+3]
    const int e0 = ty * 8;     // rows [e0..e0+7]

    // Per-thread bias (loop invariant)
    float bv[8];
    #pragma unroll
    for (int i = 0; i < 4; ++i) bv[i]     = __ldg(&bias[c0 + i]);
    #pragma unroll
    for (int i = 0; i < 4; ++i) bv[4 + i] = __ldg(&bias[64 + c0 + i]);

    const int ge = tid & 127;  // gather: which row of the tile this thread fills
    const int gh = tid >> 7;   // gather: which 64-float half of the row

    const int n_tiles = (n_rows + TE - 1) / TE;

    for (int tile = blockIdx.x; tile < n_tiles; tile += gridDim.x) {
        const int base = tile * TE;
        __syncthreads();  // Hs free to overwrite; also orders first-iter Wd writes

        // ---- Gather tile into k-major SMEM (conflict-free STS: lanes vary e) ----
        {
            int eg = base + ge;
            int row;
            if (EDGE_MODE) row = (eg < n_rows) ? __ldg(&src[eg]) : 0;
            else           row = (eg < n_rows) ? eg : 0;
            const float4* xr = (const float4*)(X + (size_t)row * HID) + gh * 16;
            #pragma unroll
            for (int q = 0; q < 16; ++q) {
                float4 v = __ldg(&xr[q]);
                int k = gh * 64 + q * 4;
                Hs[(k + 0) * TE + ge] = v.x;
                Hs[(k + 1) * TE + ge] = v.y;
                Hs[(k + 2) * TE + ge] = v.z;
                Hs[(k + 3) * TE + ge] = v.w;
            }
        }
        __syncthreads();

        // ---- Main loop: 4 edge-pairs x 8 cols of f32x2 accumulators ----
        unsigned long long acc[4][8];
        #pragma unroll
        for (int j = 0; j < 4; ++j)
            #pragma unroll
            for (int c = 0; c < 8; ++c) acc[j][c] = 0ull;

        #pragma unroll 8
        for (int k = 0; k < HID; ++k) {
            const ulonglong2 a01 = *(const ulonglong2*)&Hs[k * TE + e0];
            const ulonglong2 a23 = *(const ulonglong2*)&Hs[k * TE + e0 + 4];
            const float* wr = &Wd[k * 2 * HID];
            const ulonglong2 b01 = *(const ulonglong2*)&wr[2 * c0];
            const ulonglong2 b23 = *(const ulonglong2*)&wr[2 * c0 + 4];
            const ulonglong2 b45 = *(const ulonglong2*)&wr[128 + 2 * c0];
            const ulonglong2 b67 = *(const ulonglong2*)&wr[128 + 2 * c0 + 4];
            unsigned long long a[4] = {a01.x, a01.y, a23.x, a23.y};
            unsigned long long b[8] = {b01.x, b01.y, b23.x, b23.y,
                                       b45.x, b45.y, b67.x, b67.y};
            #pragma unroll
            for (int j = 0; j < 4; ++j)
                #pragma unroll
                for (int c = 0; c < 8; ++c)
                    acc[j][c] = ffma2(a[j], b[c], acc[j][c]);
        }

        // ---- Epilogue ----
        #pragma unroll
        for (int j = 0; j < 8; ++j) {
            const int jp = j >> 1;
            const int hi = j & 1;
            float vals[8];
            #pragma unroll
            for (int c = 0; c < 8; ++c) {
                float2 f = *(float2*)&acc[jp][c];
                vals[c] = hi ? f.y : f.x;
            }
            int r = base + e0 + j;
            if (r < n_rows) {
                if (EDGE_MODE) {
                    float nm = __ldg(&nrm[r]);
                    int   t  = __ldg(&tgt[r]);
                    float* op = out + (size_t)t * HID;
                    float m0 = nm * fmaxf(vals[0] + bv[0], 0.f);
                    float m1 = nm * fmaxf(vals[1] + bv[1], 0.f);
                    float m2 = nm * fmaxf(vals[2] + bv[2], 0.f);
                    float m3 = nm * fmaxf(vals[3] + bv[3], 0.f);
                    red_add_v4(op + c0, m0, m1, m2, m3);
                    float m4 = nm * fmaxf(vals[4] + bv[4], 0.f);
                    float m5 = nm * fmaxf(vals[5] + bv[5], 0.f);
                    float m6 = nm * fmaxf(vals[6] + bv[6], 0.f);
                    float m7 = nm * fmaxf(vals[7] + bv[7], 0.f);
                    red_add_v4(op + 64 + c0, m4, m5, m6, m7);
                } else {
                    const float* rp = resid + (size_t)r * HID;
                    float* op = out + (size_t)r * HID;
                    float4 v;
                    v.x = fmaxf(vals[0] + bv[0], 0.f) + __ldg(&rp[c0 + 0]);
                    v.y = fmaxf(vals[1] + bv[1], 0.f) + __ldg(&rp[c0 + 1]);
                    v.z = fmaxf(vals[2] + bv[2], 0.f) + __ldg(&rp[c0 + 2]);
                    v.w = fmaxf(vals[3] + bv[3], 0.f) + __ldg(&rp[c0 + 3]);
                    *(float4*)(op + c0) = v;
                    v.x = fmaxf(vals[4] + bv[4], 0.f) + __ldg(&rp[64 + c0 + 0]);
                    v.y = fmaxf(vals[5] + bv[5], 0.f) + __ldg(&rp[64 + c0 + 1]);
                    v.z = fmaxf(vals[6] + bv[6], 0.f) + __ldg(&rp[64 + c0 + 2]);
                    v.w = fmaxf(vals[7] + bv[7], 0.f) + __ldg(&rp[64 + c0 + 3]);
                    *(float4*)(op + 64 + c0) = v;
                }
            }
        }
    }
}

extern "C" void kernel_launch(void* const* d_in, const int* in_sizes, int n_in,
                              void* d_out, int out_size) {
    (void)in_sizes; (void)n_in; (void)out_size;
    const float* x      = (const float*)d_in[0];
    const int*   src    = (const int*)  d_in[1];
    const int*   tgt    = (const int*)  d_in[2];
    const float* nrm    = (const float*)d_in[3];
    const float* W_edge = (const float*)d_in[4];
    const float* b_edge = (const float*)d_in[5];
    const float* W_node = (const float*)d_in[6];
    const float* b_node = (const float*)d_in[7];
    float* out = (float*)d_out;

    void* pooled_ptr = nullptr;
    cudaGetSymbolAddress(&pooled_ptr, g_pooled);
    float* pooled = (float*)pooled_ptr;

    int nsm = 148;
    cudaDeviceGetAttribute(&nsm, cudaDevAttrMultiProcessorCount, 0);

    const size_t smem = (size_t)(HID * 2 * HID + HID * TE) * sizeof(float); // 192 KB
    cudaFuncSetAttribute(fused_gemm<true>,  cudaFuncAttributeMaxDynamicSharedMemorySize, (int)smem);
    cudaFuncSetAttribute(fused_gemm<false>, cudaFuncAttributeMaxDynamicSharedMemorySize, (int)smem);

    // 1) zero the pooled accumulator
    cudaMemsetAsync(pooled, 0, sizeof(float) * (size_t)N_NODES_C * HID, 0);

    // 2) edge GEMM + scatter-reduce
    fused_gemm<true><<<nsm, NTHREADS, smem>>>(x, W_edge, b_edge, src, tgt, nrm,
                                              nullptr, pooled, N_EDGES_C);

    // 3) node GEMM + relu + residual
    fused_gemm<false><<<nsm, NTHREADS, smem>>>(pooled, W_node, b_node, nullptr, nullptr,
                                               nullptr, x, out, N_NODES_C);
}

// round 2
// speedup vs baseline: 1.0192x; 1.0192x over previous
#include <cuda_runtime.h>
#include <cstdint>
#include <cstddef>

#define N_NODES_C 50000
#define N_EDGES_C 625000
#define HID 128
#define TE 128
#define NTHREADS 256

// 25.6 MB scratch for pooled messages (allocation-free scratch via __device__ global)
__device__ float g_pooled[(size_t)N_NODES_C * HID];

__device__ __forceinline__ unsigned long long ffma2(unsigned long long a,
                                                    unsigned long long b,
                                                    unsigned long long c) {
    unsigned long long d;
    asm("fma.rn.f32x2 %0, %1, %2, %3;" : "=l"(d) : "l"(a), "l"(b), "l"(c));
    return d;
}

__device__ __forceinline__ void red_add_v4(float* p, float a, float b, float c, float d) {
    asm volatile("red.global.add.v4.f32 [%0], {%1, %2, %3, %4};"
                 :: "l"(p), "f"(a), "f"(b), "f"(c), "f"(d) : "memory");
}

// One kernel template for both GEMMs.
// EDGE_MODE=true : rows gathered via src; epilogue = gcn_norm * relu(.+bias), red-scatter by tgt into out(=pooled)
// EDGE_MODE=false: rows are direct;      epilogue = relu(.+bias) + resid, direct store into out
template<bool EDGE_MODE>
__global__ void __launch_bounds__(NTHREADS, 1)
fused_gemm(const float* __restrict__ X,
           const float* __restrict__ W,      // [HID, HID] row-major: out[c] = sum_k in[k]*W[k*HID+c]
           const float* __restrict__ bias,   // [HID]
           const int*   __restrict__ src,
           const int*   __restrict__ tgt,
           const float* __restrict__ nrm,
           const float* __restrict__ resid,
           float*       __restrict__ out,
           int n_rows)
{
    extern __shared__ float smem[];
    float* Wd = smem;                    // HID x (2*HID): Wd[k*256 + 2c] = Wd[k*256+2c+1] = W[k][c]
    float* Hs = smem + HID * 2 * HID;    // k-major tile: Hs[k*TE + e]

    const int tid = threadIdx.x;

    // ---- Load W into duplicated layout (once per block, persistent grid) ----
    for (int i = tid; i < HID * HID / 4; i += NTHREADS) {
        float4 w = __ldg((const float4*)W + i);
        int k = (i * 4) / HID;
        int c = (i * 4) % HID;
        float* d = &Wd[k * 2 * HID + 2 * c];
        d[0] = w.x; d[1] = w.x;
        d[2] = w.y; d[3] = w.y;
        d[4] = w.z; d[5] = w.z;
        d[6] = w.w; d[7] = w.w;
    }

    const int tx = tid & 15;   // column group 0..15
    const int ty = tid >> 4;   // row group    0..15
    const int c0 = tx * 4;     // cols [c0..c0+3] and [64+c0..64+c0+3]
    const int e0 = ty * 8;     // rows [e0..e0+7]

    // Per-thread bias (loop invariant)
    float bv[8];
    #pragma unroll
    for (int i = 0; i < 4; ++i) bv[i]     = __ldg(&bias[c0 + i]);
    #pragma unroll
    for (int i = 0; i < 4; ++i) bv[4 + i] = __ldg(&bias[64 + c0 + i]);

    const int ge = tid & 127;  // gather: which row of the tile this thread fills
    const int gh = tid >> 7;   // gather: which 64-float half of the row

    const int n_tiles = (n_rows + TE - 1) / TE;

    for (int tile = blockIdx.x; tile < n_tiles; tile += gridDim.x) {
        const int base = tile * TE;
        __syncthreads();  // Hs free to overwrite; also orders first-iter Wd writes

        // ---- Gather tile into k-major SMEM (conflict-free STS: lanes vary e) ----
        {
            int eg = base + ge;
            int row;
            if (EDGE_MODE) row = (eg < n_rows) ? __ldg(&src[eg]) : 0;
            else           row = (eg < n_rows) ? eg : 0;
            const float4* xr = (const float4*)(X + (size_t)row * HID) + gh * 16;
            #pragma unroll
            for (int q = 0; q < 16; ++q) {
                float4 v = __ldg(&xr[q]);
                int k = gh * 64 + q * 4;
                Hs[(k + 0) * TE + ge] = v.x;
                Hs[(k + 1) * TE + ge] = v.y;
                Hs[(k + 2) * TE + ge] = v.z;
                Hs[(k + 3) * TE + ge] = v.w;
            }
        }
        __syncthreads();

        // ---- Main loop: 4 edge-pairs x 8 cols of f32x2 accumulators ----
        unsigned long long acc[4][8];
        #pragma unroll
        for (int j = 0; j < 4; ++j)
            #pragma unroll
            for (int c = 0; c < 8; ++c) acc[j][c] = 0ull;

        #pragma unroll 8
        for (int k = 0; k < HID; ++k) {
            const ulonglong2 a01 = *(const ulonglong2*)&Hs[k * TE + e0];
            const ulonglong2 a23 = *(const ulonglong2*)&Hs[k * TE + e0 + 4];
            const float* wr = &Wd[k * 2 * HID];
            const ulonglong2 b01 = *(const ulonglong2*)&wr[2 * c0];
            const ulonglong2 b23 = *(const ulonglong2*)&wr[2 * c0 + 4];
            const ulonglong2 b45 = *(const ulonglong2*)&wr[128 + 2 * c0];
            const ulonglong2 b67 = *(const ulonglong2*)&wr[128 + 2 * c0 + 4];
            unsigned long long a[4] = {a01.x, a01.y, a23.x, a23.y};
            unsigned long long b[8] = {b01.x, b01.y, b23.x, b23.y,
                                       b45.x, b45.y, b67.x, b67.y};
            #pragma unroll
            for (int j = 0; j < 4; ++j)
                #pragma unroll
                for (int c = 0; c < 8; ++c)
                    acc[j][c] = ffma2(a[j], b[c], acc[j][c]);
        }

        // ---- Epilogue ----
        #pragma unroll
        for (int j = 0; j < 8; ++j) {
            const int jp = j >> 1;
            const int hi = j & 1;
            float vals[8];
            #pragma unroll
            for (int c = 0; c < 8; ++c) {
                float2 f = *(float2*)&acc[jp][c];
                vals[c] = hi ? f.y : f.x;
            }
            int r = base + e0 + j;
            if (r < n_rows) {
                if (EDGE_MODE) {
                    float nm = __ldg(&nrm[r]);
                    int   t  = __ldg(&tgt[r]);
                    float* op = out + (size_t)t * HID;
                    float m0 = nm * fmaxf(vals[0] + bv[0], 0.f);
                    float m1 = nm * fmaxf(vals[1] + bv[1], 0.f);
                    float m2 = nm * fmaxf(vals[2] + bv[2], 0.f);
                    float m3 = nm * fmaxf(vals[3] + bv[3], 0.f);
                    red_add_v4(op + c0, m0, m1, m2, m3);
                    float m4 = nm * fmaxf(vals[4] + bv[4], 0.f);
                    float m5 = nm * fmaxf(vals[5] + bv[5], 0.f);
                    float m6 = nm * fmaxf(vals[6] + bv[6], 0.f);
                    float m7 = nm * fmaxf(vals[7] + bv[7], 0.f);
                    red_add_v4(op + 64 + c0, m4, m5, m6, m7);
                } else {
                    const float* rp = resid + (size_t)r * HID;
                    float* op = out + (size_t)r * HID;
                    float4 v;
                    v.x = fmaxf(vals[0] + bv[0], 0.f) + __ldg(&rp[c0 + 0]);
                    v.y = fmaxf(vals[1] + bv[1], 0.f) + __ldg(&rp[c0 + 1]);
                    v.z = fmaxf(vals[2] + bv[2], 0.f) + __ldg(&rp[c0 + 2]);
                    v.w = fmaxf(vals[3] + bv[3], 0.f) + __ldg(&rp[c0 + 3]);
                    *(float4*)(op + c0) = v;
                    v.x = fmaxf(vals[4] + bv[4], 0.f) + __ldg(&rp[64 + c0 + 0]);
                    v.y = fmaxf(vals[5] + bv[5], 0.f) + __ldg(&rp[64 + c0 + 1]);
                    v.z = fmaxf(vals[6] + bv[6], 0.f) + __ldg(&rp[64 + c0 + 2]);
                    v.w = fmaxf(vals[7] + bv[7], 0.f) + __ldg(&rp[64 + c0 + 3]);
                    *(float4*)(op + 64 + c0) = v;
                }
            }
        }
    }
}

extern "C" void kernel_launch(void* const* d_in, const int* in_sizes, int n_in,
                              void* d_out, int out_size) {
    (void)in_sizes; (void)n_in; (void)out_size;
    const float* x      = (const float*)d_in[0];
    const int*   src    = (const int*)  d_in[1];
    const int*   tgt    = (const int*)  d_in[2];
    const float* nrm    = (const float*)d_in[3];
    const float* W_edge = (const float*)d_in[4];
    const float* b_edge = (const float*)d_in[5];
    const float* W_node = (const float*)d_in[6];
    const float* b_node = (const float*)d_in[7];
    float* out = (float*)d_out;

    void* pooled_ptr = nullptr;
    cudaGetSymbolAddress(&pooled_ptr, g_pooled);
    float* pooled = (float*)pooled_ptr;

    int nsm = 148;
    cudaDeviceGetAttribute(&nsm, cudaDevAttrMultiProcessorCount, 0);

    const size_t smem = (size_t)(HID * 2 * HID + HID * TE) * sizeof(float); // 192 KB
    cudaFuncSetAttribute(fused_gemm<true>,  cudaFuncAttributeMaxDynamicSharedMemorySize, (int)smem);
    cudaFuncSetAttribute(fused_gemm<false>, cudaFuncAttributeMaxDynamicSharedMemorySize, (int)smem);

    // 1) zero the pooled accumulator
    cudaMemsetAsync(pooled, 0, sizeof(float) * (size_t)N_NODES_C * HID, 0);

    // 2) edge GEMM + scatter-reduce
    fused_gemm<true><<<nsm, NTHREADS, smem>>>(x, W_edge, b_edge, src, tgt, nrm,
                                              nullptr, pooled, N_EDGES_C);

    // 3) node GEMM + relu + residual
    fused_gemm<false><<<nsm, NTHREADS, smem>>>(pooled, W_node, b_node, nullptr, nullptr,
                                               nullptr, x, out, N_NODES_C);
}